// round 4
// baseline (speedup 1.0000x reference)
#include <cuda_runtime.h>
#include <math.h>
#include <stdint.h>

#define Bsz 256
#define Ssz 2048
#define Dsz 64
#define Hsz 256
#define NCTA 128          // persistent kernel CTAs (16 clusters x 8)
#define RTHREADS 128
#define WPAD 260          // smem row stride for state tiles (floats)

// ---------------- device scratch (static: no allocations allowed) ----------------
__device__ float g_pre0[(size_t)Ssz * Bsz * Hsz];   // [s][b][h]  (512 MB)
__device__ float g_h0[2][Bsz * Hsz];                // double-buffered layer-0 state [b][h]
__device__ float g_h1[2][Bsz * Hsz];                // double-buffered layer-1 state [b][h]

// ---------------- init: zero state seed buffers (graph replays deterministic) ----------------
__global__ void init_kernel() {
    int idx = blockIdx.x * blockDim.x + threadIdx.x;
    if (idx < Bsz * Hsz) {
        g_h0[1][idx] = 0.0f;   // read as h0_{-1} at iteration 0
        g_h1[1][idx] = 0.0f;   // read as h1_{-1} at iteration 1
    }
}

// ---------------- pre0 = x @ W_ih0^T + (b_ih0 + b_hh0) ----------------
__global__ void pre0_kernel(const float* __restrict__ x,
                            const float* __restrict__ Wih0,
                            const float* __restrict__ bih0,
                            const float* __restrict__ bhh0) {
    __shared__ float sW[128 * 68];
    __shared__ float sX[16 * 68];

    const int s   = blockIdx.x;
    const int b0  = blockIdx.y * 16;
    const int tid = threadIdx.x;

    for (int i = tid; i < 16 * Dsz; i += 256) {
        int r = i >> 6, k = i & 63;
        sX[r * 68 + k] = x[((size_t)(b0 + r) * Ssz + s) * Dsz + k];
    }

    const int g  = tid >> 7;
    const int hl = tid & 127;

    for (int half = 0; half < 2; ++half) {
        __syncthreads();
        for (int i = tid; i < 128 * Dsz; i += 256) {
            int h = i >> 6, k = i & 63;
            sW[h * 68 + k] = Wih0[(size_t)(half * 128 + h) * Dsz + k];
        }
        __syncthreads();

        float acc[8];
#pragma unroll
        for (int r = 0; r < 8; ++r) acc[r] = 0.0f;

#pragma unroll 4
        for (int kq = 0; kq < Dsz / 4; ++kq) {
            float4 w = *(const float4*)(sW + hl * 68 + kq * 4);
#pragma unroll
            for (int r = 0; r < 8; ++r) {
                float4 xv = *(const float4*)(sX + (g * 8 + r) * 68 + kq * 4);
                acc[r] += w.x * xv.x + w.y * xv.y + w.z * xv.z + w.w * xv.w;
            }
        }

        const int hglob = half * 128 + hl;
        const float bsum = bih0[hglob] + bhh0[hglob];
#pragma unroll
        for (int r = 0; r < 8; ++r)
            g_pre0[((size_t)s * Bsz + b0 + g * 8 + r) * Hsz + hglob] = acc[r] + bsum;
    }
}

// ---------------- cluster-scope step barrier ----------------
// Writer side: st.global data, __threadfence() (gpu scope -> MEMBAR + CCTL.IVALL,
// also invalidates our L1 so post-wait LDGs of sibling state are fresh), then
// cluster arrive/wait. Only the 8 CTAs of one b-group synchronize.
__device__ __forceinline__ void cluster_step_barrier() {
    __threadfence();
    asm volatile("barrier.cluster.arrive.aligned;" ::: "memory");
    asm volatile("barrier.cluster.wait.aligned;"   ::: "memory");
}

// ---------------- persistent fused recurrence ----------------
// 16 clusters of 8 CTAs. Cluster = one 16-row batch group; CTA within cluster
// owns 32 h-columns of BOTH layers. Iteration i: h0_i (i<S) and h1_{i-1} (i>=1).
__global__ void __launch_bounds__(RTHREADS, 1) __cluster_dims__(8, 1, 1)
rnn_kernel(const float* __restrict__ Whh0,
           const float* __restrict__ Wih1,
           const float* __restrict__ Whh1,
           const float* __restrict__ bih1,
           const float* __restrict__ bhh1) {
    extern __shared__ float smem[];
    // weights: [kq][col][4] -> contiguous 512B per (warp, kq): conflict-free LDS.128
    float* sW0  = smem;                    // 64*128 floats
    float* sWi1 = sW0  + 64 * 128;
    float* sWh1 = sWi1 + 64 * 128;
    float* sH0  = sWh1 + 64 * 128;         // [16][WPAD]
    float* sH1  = sH0  + 16 * WPAD;        // [16][WPAD]

    const int cta  = blockIdx.x;
    const int b0   = (cta >> 3) * 16;      // cluster id * 16
    const int h0c  = (cta & 7) * 32;       // rank within cluster * 32
    const int lane = threadIdx.x & 31;
    const int warp = threadIdx.x >> 5;
    const int r0   = warp * 4;

    // ---- one-time weight load: global [col][k] -> smem [kq][col][4] ----
    {
        for (int it = threadIdx.x; it < 32 * 64; it += RTHREADS) {
            const int col = it >> 6;          // 0..31  (64 consecutive threads -> same col: coalesced)
            const int kq  = it & 63;          // 0..63
            const size_t gi = (size_t)(h0c + col) * Hsz + kq * 4;
            const int    si = (kq * 32 + col) * 4;
            *(float4*)(sW0  + si) = *(const float4*)(Whh0 + gi);
            *(float4*)(sWi1 + si) = *(const float4*)(Wih1 + gi);
            *(float4*)(sWh1 + si) = *(const float4*)(Whh1 + gi);
        }
    }
    const float bias1 = bih1[h0c + lane] + bhh1[h0c + lane];
    __syncthreads();

    // staging thread mapping: row = tid>>3, 8 threads cover 128B contiguous per q
    const int srow = threadIdx.x >> 3;          // 0..15
    const int soff = (threadIdx.x & 7) * 4;     // float offset within 32-float chunk

    // prologue: prefetch pre0 for step 0
    float p[4];
#pragma unroll
    for (int r = 0; r < 4; ++r)
        p[r] = g_pre0[((size_t)0 * Bsz + b0 + r0 + r) * Hsz + h0c + lane];

    for (int i = 0; i <= Ssz; ++i) {
        // ---- stage previous states into SMEM (conflict-free, coalesced) ----
        {
            const float* src = g_h0[(i + 1) & 1] + (size_t)(b0 + srow) * Hsz + soff;
            float* dst = sH0 + srow * WPAD + soff;
#pragma unroll
            for (int q = 0; q < 8; ++q)
                *(float4*)(dst + q * 32) = *(const float4*)(src + q * 32);
        }
        if (i >= 1) {
            const float* src = g_h1[i & 1] + (size_t)(b0 + srow) * Hsz + soff;
            float* dst = sH1 + srow * WPAD + soff;
#pragma unroll
            for (int q = 0; q < 8; ++q)
                *(float4*)(dst + q * 32) = *(const float4*)(src + q * 32);
        }
        __syncthreads();

        // ---- h0_i = tanh(pre0_i + h0_{i-1} @ Whh0^T) ----
        if (i < Ssz) {
            float a[4] = {0.f, 0.f, 0.f, 0.f};
#pragma unroll 4
            for (int kq = 0; kq < 64; ++kq) {
                float4 w = *(const float4*)(sW0 + (kq * 32 + lane) * 4);
#pragma unroll
                for (int r = 0; r < 4; ++r) {
                    float4 xv = *(const float4*)(sH0 + (r0 + r) * WPAD + kq * 4);
                    a[r] += w.x * xv.x + w.y * xv.y + w.z * xv.z + w.w * xv.w;
                }
            }
            float* dst = g_h0[i & 1];
#pragma unroll
            for (int r = 0; r < 4; ++r)
                dst[(size_t)(b0 + r0 + r) * Hsz + h0c + lane] = tanhf(p[r] + a[r]);
        }

        // ---- h1_{i-1} = tanh(b1 + h0_{i-1} @ Wih1^T + h1_{i-2} @ Whh1^T) ----
        if (i >= 1) {
            float a[4] = {bias1, bias1, bias1, bias1};
#pragma unroll 4
            for (int kq = 0; kq < 64; ++kq) {
                float4 w = *(const float4*)(sWi1 + (kq * 32 + lane) * 4);
#pragma unroll
                for (int r = 0; r < 4; ++r) {
                    float4 xv = *(const float4*)(sH0 + (r0 + r) * WPAD + kq * 4);
                    a[r] += w.x * xv.x + w.y * xv.y + w.z * xv.z + w.w * xv.w;
                }
            }
#pragma unroll 4
            for (int kq = 0; kq < 64; ++kq) {
                float4 w = *(const float4*)(sWh1 + (kq * 32 + lane) * 4);
#pragma unroll
                for (int r = 0; r < 4; ++r) {
                    float4 xv = *(const float4*)(sH1 + (r0 + r) * WPAD + kq * 4);
                    a[r] += w.x * xv.x + w.y * xv.y + w.z * xv.z + w.w * xv.w;
                }
            }
            float* dst = g_h1[(i - 1) & 1];
#pragma unroll
            for (int r = 0; r < 4; ++r)
                dst[(size_t)(b0 + r0 + r) * Hsz + h0c + lane] = tanhf(a[r]);
        }

        // ---- prefetch next step's pre0 (overlaps DRAM latency with barrier) ----
        if (i + 1 < Ssz) {
#pragma unroll
            for (int r = 0; r < 4; ++r)
                p[r] = g_pre0[((size_t)(i + 1) * Bsz + b0 + r0 + r) * Hsz + h0c + lane];
        }

        cluster_step_barrier();
    }
}

// ---------------- head: out = sigmoid(h1_last @ W_out^T + b_out) ----------------
__global__ void head_kernel(const float* __restrict__ Wout,
                            const float* __restrict__ bout,
                            float* __restrict__ out) {
    const int warp = threadIdx.x >> 5;
    const int lane = threadIdx.x & 31;
    const int b = blockIdx.x * 8 + warp;
    const float* h = g_h1[(Ssz - 1) & 1] + (size_t)b * Hsz;
    float s = 0.0f;
#pragma unroll
    for (int k = lane; k < Hsz; k += 32) s += h[k] * Wout[k];
#pragma unroll
    for (int o = 16; o > 0; o >>= 1) s += __shfl_down_sync(0xFFFFFFFFu, s, o);
    if (lane == 0) out[b] = 1.0f / (1.0f + expf(-(s + bout[0])));
}

// ---------------- launch ----------------
extern "C" void kernel_launch(void* const* d_in, const int* in_sizes, int n_in,
                              void* d_out, int out_size) {
    const float* x    = (const float*)d_in[0];
    const float* Wih0 = (const float*)d_in[1];
    const float* Whh0 = (const float*)d_in[2];
    const float* bih0 = (const float*)d_in[3];
    const float* bhh0 = (const float*)d_in[4];
    const float* Wih1 = (const float*)d_in[5];
    const float* Whh1 = (const float*)d_in[6];
    const float* bih1 = (const float*)d_in[7];
    const float* bhh1 = (const float*)d_in[8];
    const float* Wout = (const float*)d_in[9];
    const float* bout = (const float*)d_in[10];
    float* out = (float*)d_out;

    const int rnn_smem = (3 * 64 * 128 + 2 * 16 * WPAD) * (int)sizeof(float); // 131,584 B
    static int configured = 0;
    if (!configured) {
        cudaFuncSetAttribute(rnn_kernel, cudaFuncAttributeMaxDynamicSharedMemorySize, rnn_smem);
        configured = 1;
    }

    init_kernel<<<(Bsz * Hsz + 255) / 256, 256>>>();
    pre0_kernel<<<dim3(Ssz, Bsz / 16), 256>>>(x, Wih0, bih0, bhh0);
    rnn_kernel<<<NCTA, RTHREADS, rnn_smem>>>(Whh0, Wih1, Whh1, bih1, bhh1);
    head_kernel<<<Bsz / 8, 256>>>(Wout, bout, out);
}

// round 5
// speedup vs baseline: 1.3320x; 1.3320x over previous
#include <cuda_runtime.h>
#include <math.h>
#include <stdint.h>

#define Bsz 256
#define Ssz 2048
#define Dsz 64
#define Hsz 256
#define NCTA 128          // persistent CTAs, 1/SM, all co-resident
#define NTHR 256          // 8 warps: 0-3 khalf0, 4-7 khalf1
#define WPAD 260          // state row stride (floats); 260*4B = 65*16B -> float4 aligned

// ---------------- device scratch ----------------
__device__ float g_pre0p[(size_t)NCTA * Ssz * 512];  // private pre0 [cta][s][row16][lane32]
__device__ float g_h0[2][Bsz * Hsz];                 // layer-0 state, double buffered
__device__ float g_h1[2][Bsz * Hsz];                 // layer-1 state, double buffered
__device__ unsigned int g_flags[NCTA];               // barrier flags (monotonic per launch)

// ---------------- grid barrier (R2-proven flag style) ----------------
__device__ __forceinline__ void grid_barrier(unsigned int val) {
    __threadfence();                                  // release (also CCTL.IVALL)
    __syncthreads();
    if (threadIdx.x == 0) g_flags[blockIdx.x] = val;
    if (threadIdx.x < NCTA) {
        volatile unsigned int* p = &g_flags[threadIdx.x];
        while (*p < val) { }
    }
    __threadfence();                                  // acquire: invalidate L1 for sibling state
    __syncthreads();
}

__global__ void __launch_bounds__(NTHR, 1)
fused_kernel(const float* __restrict__ x,
             const float* __restrict__ Wih0,
             const float* __restrict__ Whh0,
             const float* __restrict__ bih0,
             const float* __restrict__ bhh0,
             const float* __restrict__ Wih1,
             const float* __restrict__ Whh1,
             const float* __restrict__ bih1,
             const float* __restrict__ bhh1,
             const float* __restrict__ Wout,
             const float* __restrict__ bout,
             float* __restrict__ out) {
    extern __shared__ float smem[];
    float* sW0   = smem;                      //  8192 f : Whh0 [kq][col][4]
    float* sWi1  = sW0   + 8192;              //  8192 f : Wih1
    float* sWh1  = sWi1  + 8192;              //  8192 f : Whh1
    float* sH0   = sWh1  + 8192;              // 16*WPAD : h0_{i-1}
    float* sH1   = sH0   + 16 * WPAD;         // 16*WPAD : h1_{i-2}
    float* sRedA = sH1   + 16 * WPAD;         // 16*33   : h0 partials
    float* sRedB = sRedA + 16 * 33;           // 16*33   : h1 partials
    float* sX    = sRedB + 16 * 33;           // 16*8*68 : pre0 x staging

    const int tid   = threadIdx.x;
    const int cta   = blockIdx.x;
    const int b0    = (cta >> 3) * 16;        // 16 batch rows
    const int h0c   = (cta & 7) * 32;         // 32 h columns
    const int lane  = tid & 31;
    const int warp  = tid >> 5;               // 0..7
    const int khalf = warp >> 2;              // 0/1 : k range [khalf*128, +128)
    const int r0    = (warp & 3) * 4;         // 4 rows per warp

    // ---- launch-entry reset (safe: >1M cycles of pre0 before first barrier) ----
    if (tid == 0) g_flags[cta] = 0u;
    // zero own tiles of the seed state buffers
    if (tid < 32) {
        for (int r = 0; r < 16; ++r) {
            g_h0[1][(size_t)(b0 + r) * Hsz + h0c + tid] = 0.0f;
            g_h1[1][(size_t)(b0 + r) * Hsz + h0c + tid] = 0.0f;
        }
    }
    __threadfence();

    // ================= phase 1: pre0_priv = x @ Wih0^T + (b_ih0+b_hh0) =================
    {
        // per-thread weights for column h0c+lane (64 floats in regs)
        float4 wih[16];
#pragma unroll
        for (int kq = 0; kq < 16; ++kq)
            wih[kq] = *(const float4*)(Wih0 + (size_t)(h0c + lane) * Dsz + kq * 4);
        const float bsum = bih0[h0c + lane] + bhh0[h0c + lane];

        const int xrow = tid >> 4;        // 0..15
        const int t16  = tid & 15;

        for (int blk = 0; blk < Ssz / 8; ++blk) {
            const int s0 = blk * 8;
            __syncthreads();   // protect sX reuse
            // stage x rows: 8 steps x 64 d contiguous per row
            {
                const float* src = x + ((size_t)(b0 + xrow) * Ssz + s0) * Dsz;
#pragma unroll
                for (int q = 0; q < 8; ++q) {
                    const int idx = t16 + q * 16;                 // float4 index 0..127
                    float4 v = *(const float4*)(src + idx * 4);
                    *(float4*)(sX + xrow * 544 + (idx >> 4) * 68 + (idx & 15) * 4) = v;
                }
            }
            __syncthreads();
#pragma unroll
            for (int sl = 0; sl < 8; ++sl) {
                float a0 = 0.f, a1 = 0.f;
                const float* xr0 = sX + (warp * 2 + 0) * 544 + sl * 68;
                const float* xr1 = sX + (warp * 2 + 1) * 544 + sl * 68;
#pragma unroll
                for (int kq = 0; kq < 16; ++kq) {
                    float4 w  = wih[kq];
                    float4 v0 = *(const float4*)(xr0 + kq * 4);
                    float4 v1 = *(const float4*)(xr1 + kq * 4);
                    a0 += w.x * v0.x + w.y * v0.y + w.z * v0.z + w.w * v0.w;
                    a1 += w.x * v1.x + w.y * v1.y + w.z * v1.z + w.w * v1.w;
                }
                float* dst = g_pre0p + ((size_t)cta * Ssz + s0 + sl) * 512;
                dst[(warp * 2 + 0) * 32 + lane] = a0 + bsum;
                dst[(warp * 2 + 1) * 32 + lane] = a1 + bsum;
            }
        }
    }

    // ---- one-time recurrence weight load: [col][k] -> smem [kq][col][4] ----
    for (int it = tid; it < 32 * 64; it += NTHR) {
        const int col = it >> 6;
        const int kq  = it & 63;
        const size_t gi = (size_t)(h0c + col) * Hsz + kq * 4;
        const int    si = (kq * 32 + col) * 4;
        *(float4*)(sW0  + si) = *(const float4*)(Whh0 + gi);
        *(float4*)(sWi1 + si) = *(const float4*)(Wih1 + gi);
        *(float4*)(sWh1 + si) = *(const float4*)(Whh1 + gi);
    }
    const float bias1 = bih1[h0c + lane] + bhh1[h0c + lane];

    grid_barrier(1u);   // zeroing + pre0 done everywhere

    // ================= phase 2: fused two-layer recurrence =================
    const int srow = tid >> 4;          // staging: row 0..15
    const int sc0  = tid & 15;          // 16 threads per row

    for (int i = 0; i <= Ssz; ++i) {
        // ---- stage previous states (coalesced LDG.128 / conflict-free STS.128) ----
        {
            const float* src = g_h0[(i + 1) & 1] + (size_t)(b0 + srow) * Hsz;
            float* dst = sH0 + srow * WPAD;
#pragma unroll
            for (int q = 0; q < 4; ++q) {
                const int idx = sc0 + q * 16;
                *(float4*)(dst + idx * 4) = *(const float4*)(src + idx * 4);
            }
        }
        if (i >= 1) {
            const float* src = g_h1[i & 1] + (size_t)(b0 + srow) * Hsz;
            float* dst = sH1 + srow * WPAD;
#pragma unroll
            for (int q = 0; q < 4; ++q) {
                const int idx = sc0 + q * 16;
                *(float4*)(dst + idx * 4) = *(const float4*)(src + idx * 4);
            }
        }
        // prefetch pre0 slice (khalf0 warps finalize h0 and need it)
        float p[4];
        if (i < Ssz && khalf == 0) {
            const float* pp = g_pre0p + ((size_t)cta * Ssz + i) * 512;
#pragma unroll
            for (int r = 0; r < 4; ++r) p[r] = pp[(r0 + r) * 32 + lane];
        }
        __syncthreads();

        // ---- phase A: h0 partials over own k half ----
        float accA[4] = {0.f, 0.f, 0.f, 0.f};
        if (i < Ssz) {
            const int kqb = khalf * 32;
#pragma unroll 4
            for (int kq = kqb; kq < kqb + 32; ++kq) {
                float4 w = *(const float4*)(sW0 + (kq * 32 + lane) * 4);
#pragma unroll
                for (int r = 0; r < 4; ++r) {
                    float4 v = *(const float4*)(sH0 + (r0 + r) * WPAD + kq * 4);
                    accA[r] += w.x * v.x + w.y * v.y + w.z * v.z + w.w * v.w;
                }
            }
            if (khalf == 1) {
#pragma unroll
                for (int r = 0; r < 4; ++r) sRedA[(r0 + r) * 33 + lane] = accA[r];
            }
        }
        __syncthreads();   // sync1

        // khalf0 finalizes h0
        if (i < Ssz && khalf == 0) {
            float* dst = g_h0[i & 1];
#pragma unroll
            for (int r = 0; r < 4; ++r) {
                float v = tanhf(p[r] + accA[r] + sRedA[(r0 + r) * 33 + lane]);
                dst[(size_t)(b0 + r0 + r) * Hsz + h0c + lane] = v;
            }
        }

        // ---- phase B: layer-1 partials over own k half ----
        float accB[4] = {0.f, 0.f, 0.f, 0.f};
        if (i >= 1) {
            const int kqb = khalf * 32;
#pragma unroll 4
            for (int kq = kqb; kq < kqb + 32; ++kq) {
                float4 w = *(const float4*)(sWi1 + (kq * 32 + lane) * 4);
#pragma unroll
                for (int r = 0; r < 4; ++r) {
                    float4 v = *(const float4*)(sH0 + (r0 + r) * WPAD + kq * 4);
                    accB[r] += w.x * v.x + w.y * v.y + w.z * v.z + w.w * v.w;
                }
            }
#pragma unroll 4
            for (int kq = kqb; kq < kqb + 32; ++kq) {
                float4 w = *(const float4*)(sWh1 + (kq * 32 + lane) * 4);
#pragma unroll
                for (int r = 0; r < 4; ++r) {
                    float4 v = *(const float4*)(sH1 + (r0 + r) * WPAD + kq * 4);
                    accB[r] += w.x * v.x + w.y * v.y + w.z * v.z + w.w * v.w;
                }
            }
            if (khalf == 0) {
#pragma unroll
                for (int r = 0; r < 4; ++r) sRedB[(r0 + r) * 33 + lane] = accB[r];
            }
        }
        __syncthreads();   // sync2

        // khalf1 finalizes h1
        if (i >= 1 && khalf == 1) {
            float* dst = g_h1[(i - 1) & 1];
#pragma unroll
            for (int r = 0; r < 4; ++r) {
                float v = tanhf(bias1 + accB[r] + sRedB[(r0 + r) * 33 + lane]);
                dst[(size_t)(b0 + r0 + r) * Hsz + h0c + lane] = v;
            }
        }

        grid_barrier((unsigned int)(i + 2));
    }

    // ================= phase 3: head (16 CTAs, one per batch group) =================
    if ((cta & 7) == 0) {
        const float bo = bout[0];
#pragma unroll
        for (int rr = 0; rr < 2; ++rr) {
            const int b = b0 + warp * 2 + rr;
            const float* h = g_h1[(Ssz - 1) & 1] + (size_t)b * Hsz;
            float s = 0.0f;
#pragma unroll
            for (int j = 0; j < 8; ++j) s += h[lane + 32 * j] * Wout[lane + 32 * j];
#pragma unroll
            for (int o = 16; o > 0; o >>= 1) s += __shfl_down_sync(0xFFFFFFFFu, s, o);
            if (lane == 0) out[b] = 1.0f / (1.0f + expf(-(s + bo)));
        }
    }
}

// ---------------- launch ----------------
extern "C" void kernel_launch(void* const* d_in, const int* in_sizes, int n_in,
                              void* d_out, int out_size) {
    const float* x    = (const float*)d_in[0];
    const float* Wih0 = (const float*)d_in[1];
    const float* Whh0 = (const float*)d_in[2];
    const float* bih0 = (const float*)d_in[3];
    const float* bhh0 = (const float*)d_in[4];
    const float* Wih1 = (const float*)d_in[5];
    const float* Whh1 = (const float*)d_in[6];
    const float* bih1 = (const float*)d_in[7];
    const float* bhh1 = (const float*)d_in[8];
    const float* Wout = (const float*)d_in[9];
    const float* bout = (const float*)d_in[10];
    float* out = (float*)d_out;

    // smem: 3*8192 + 2*16*260 + 2*16*33 + 16*8*68 floats
    const int smem_bytes = (3 * 8192 + 2 * 16 * WPAD + 2 * 16 * 33 + 16 * 8 * 68) * (int)sizeof(float);
    static int configured = 0;
    if (!configured) {
        cudaFuncSetAttribute(fused_kernel, cudaFuncAttributeMaxDynamicSharedMemorySize, smem_bytes);
        configured = 1;
    }

    fused_kernel<<<NCTA, NTHR, smem_bytes>>>(x, Wih0, Whh0, bih0, bhh0,
                                             Wih1, Whh1, bih1, bhh1,
                                             Wout, bout, out);
}

// round 6
// speedup vs baseline: 1.5471x; 1.1614x over previous
#include <cuda_runtime.h>
#include <math.h>
#include <stdint.h>

#define Bsz 256
#define Ssz 2048
#define Dsz 64
#define Hsz 256
#define NCTA 128          // persistent CTAs, 1/SM, all co-resident
#define NTHR 768          // 24 warps = 3 matmuls x 4 rowquads x 2 khalves
#define WPAD 260          // state row stride (floats)

// ---------------- device scratch ----------------
__device__ float g_pre0p[(size_t)NCTA * Ssz * 512];  // private pre0 [cta][s][row16][lane32]
__device__ float g_h0[2][Bsz * Hsz];                 // layer-0 state, double buffered
__device__ float g_h1[2][Bsz * Hsz];                 // layer-1 state, double buffered
__device__ unsigned int g_flags[NCTA];               // barrier flags (monotonic ACROSS launches)

__device__ __forceinline__ float tanh_fast(float x) {
    float y; asm("tanh.approx.f32 %0, %1;" : "=f"(y) : "f"(x)); return y;
}

__global__ void __launch_bounds__(NTHR, 1)
fused_kernel(const float* __restrict__ x,
             const float* __restrict__ Wih0,
             const float* __restrict__ Whh0,
             const float* __restrict__ bih0,
             const float* __restrict__ bhh0,
             const float* __restrict__ Wih1,
             const float* __restrict__ Whh1,
             const float* __restrict__ bih1,
             const float* __restrict__ bhh1,
             const float* __restrict__ Wout,
             const float* __restrict__ bout,
             float* __restrict__ out) {
    extern __shared__ float smem[];
    float* sW   = smem;                      // 3 * 8192 f : weights [m][kq][col][4]
    float* sH0  = sW  + 3 * 8192;            // [16][WPAD]  h0_{i-1}
    float* sH1  = sH0 + 16 * WPAD;           // [16][WPAD]  h1_{i-2}
    float* sRed = sH1 + 16 * WPAD;           // 4 tiles of [16][33] partials

    const int tid  = threadIdx.x;
    const int cta  = blockIdx.x;
    const int b0   = (cta >> 3) * 16;        // 16 batch rows
    const int h0c  = (cta & 7) * 32;         // 32 h columns
    const int lane = tid & 31;
    const int warp = tid >> 5;               // 0..23
    const int m    = warp % 3;               // matmul: 0=Whh0, 1=Wih1, 2=Whh1
    const int rq   = (warp / 3) & 3;         // row quad
    const int kh   = warp / 12;              // k half
    const int r0   = rq * 4;

    // ---- barrier bases: flags are monotonic across launches (no reset race) ----
    const unsigned int base0 = (tid == 0) ? g_flags[cta] : 0u;
    unsigned int baseP = 0u;
    if (tid < NCTA) baseP = g_flags[tid];
    __syncthreads();   // bases read before anyone stores

    // ---- zero own tiles of the seed state buffers (L2-coherent stores) ----
    if (tid < 32) {
        for (int r = 0; r < 16; ++r) {
            __stcg(&g_h0[1][(size_t)(b0 + r) * Hsz + h0c + tid], 0.0f);
            __stcg(&g_h1[1][(size_t)(b0 + r) * Hsz + h0c + tid], 0.0f);
        }
    }

    // ================= phase 1: pre0_priv = x @ Wih0^T + (b_ih0+b_hh0) =================
    {
        // stage Wih0 tile as [kq16][col32][4] into sW
        for (int it = tid; it < 32 * 16; it += NTHR) {
            const int col = it >> 4, kq = it & 15;
            *(float4*)(sW + (kq * 32 + col) * 4) =
                *(const float4*)(Wih0 + (size_t)(h0c + col) * Dsz + kq * 4);
        }
        __syncthreads();
        const float bsum = bih0[h0c + lane] + bhh0[h0c + lane];

        for (int s = warp; s < Ssz; s += 24) {
            float* dst = g_pre0p + ((size_t)cta * Ssz + s) * 512;
#pragma unroll 2
            for (int r = 0; r < 16; ++r) {
                const float4* xr = (const float4*)(x + ((size_t)(b0 + r) * Ssz + s) * Dsz);
                float a = 0.0f;
#pragma unroll
                for (int c2 = 0; c2 < 2; ++c2) {
                    float4 xv[8];
#pragma unroll
                    for (int q = 0; q < 8; ++q) xv[q] = __ldg(xr + c2 * 8 + q);
#pragma unroll
                    for (int q = 0; q < 8; ++q) {
                        float4 w = *(const float4*)(sW + ((c2 * 8 + q) * 32 + lane) * 4);
                        a += w.x * xv[q].x + w.y * xv[q].y + w.z * xv[q].z + w.w * xv[q].w;
                    }
                }
                dst[r * 32 + lane] = a + bsum;
            }
        }
        __syncthreads();   // sW about to be overwritten
    }

    // ---- one-time recurrence weight load: [col][k] -> smem [m][kq][col][4] ----
    for (int it = tid; it < 32 * 64; it += NTHR) {
        const int col = it >> 6, kq = it & 63;
        const size_t gi = (size_t)(h0c + col) * Hsz + kq * 4;
        const int    si = (kq * 32 + col) * 4;
        *(float4*)(sW + 0 * 8192 + si) = *(const float4*)(Whh0 + gi);
        *(float4*)(sW + 1 * 8192 + si) = *(const float4*)(Wih1 + gi);
        *(float4*)(sW + 2 * 8192 + si) = *(const float4*)(Whh1 + gi);
    }
    const float bias1 = bih1[h0c + lane] + bhh1[h0c + lane];

    // ---- grid barrier helper (flag style, monotonic values) ----
#define GRID_BARRIER(VAL) do {                                             \
        __threadfence();                                                   \
        __syncthreads();                                                   \
        if (tid == 0) g_flags[cta] = base0 + (VAL);                        \
        if (tid < NCTA) {                                                  \
            volatile unsigned int* pf = &g_flags[tid];                     \
            const unsigned int tgt = baseP + (VAL);                        \
            while ((int)(*pf - tgt) < 0) { }                               \
        }                                                                  \
        __syncthreads();                                                   \
    } while (0)

    GRID_BARRIER(1u);   // zero-seeds + pre0 visible everywhere

    // ================= phase 2: fused two-layer recurrence =================
    // per-warp constant pointers
    const float* Wp = sW + m * 8192 + kh * 4096;              // [kq32][col][4] slice
    const float* Sbase = (m == 2) ? sH1 : sH0;
    const float* Sp = Sbase + r0 * WPAD + kh * 128;
    float* redTile = sRed + ((m == 0) ? 0 : (m == 1) ? 1 : (2 + kh)) * (16 * 33);

    for (int i = 0; i <= Ssz; ++i) {
        // ---- stage previous states into SMEM (L2-coherent loads) ----
        if (tid < 512) {
            const int row = tid >> 5, cp = tid & 31;
            const float* src = g_h0[(i + 1) & 1] + (size_t)(b0 + row) * Hsz;
            float* dst = sH0 + row * WPAD;
            *(float4*)(dst + cp * 4)        = __ldcg((const float4*)(src + cp * 4));
            *(float4*)(dst + (cp + 32) * 4) = __ldcg((const float4*)(src + (cp + 32) * 4));
        } else if (i >= 1) {
            const int t = tid - 512, row = t >> 4, c16 = t & 15;
            const float* src = g_h1[i & 1] + (size_t)(b0 + row) * Hsz;
            float* dst = sH1 + row * WPAD;
#pragma unroll
            for (int q = 0; q < 4; ++q)
                *(float4*)(dst + (c16 + q * 16) * 4) =
                    __ldcg((const float4*)(src + (c16 + q * 16) * 4));
        }
        // pre0 prefetch for h0 finalizers (m==0, kh==0)
        float p[4];
        if (m == 0 && kh == 0 && i < Ssz) {
            const float* pp = g_pre0p + ((size_t)cta * Ssz + i) * 512;
#pragma unroll
            for (int r = 0; r < 4; ++r) p[r] = pp[(r0 + r) * 32 + lane];
        }
        __syncthreads();

        // ---- single merged compute phase: all 3 matmuls concurrently ----
        float acc[4] = {0.f, 0.f, 0.f, 0.f};
        const bool active = (m == 0) ? (i < Ssz) : (i >= 1);
        if (active) {
#pragma unroll 4
            for (int kq = 0; kq < 32; ++kq) {
                float4 w = *(const float4*)(Wp + (kq * 32 + lane) * 4);
#pragma unroll
                for (int r = 0; r < 4; ++r) {
                    float4 v = *(const float4*)(Sp + r * WPAD + kq * 4);
                    acc[r] += w.x * v.x + w.y * v.y + w.z * v.z + w.w * v.w;
                }
            }
            // partial writers (everything except the two finalizer groups)
            if (!(kh == 0 && m <= 1)) {
#pragma unroll
                for (int r = 0; r < 4; ++r) redTile[(r0 + r) * 33 + lane] = acc[r];
            }
        }
        __syncthreads();

        // ---- finalize ----
        if (m == 0 && kh == 0 && i < Ssz) {            // h0_i
            float* dst = g_h0[i & 1];
#pragma unroll
            for (int r = 0; r < 4; ++r) {
                float v = tanh_fast(p[r] + acc[r] + sRed[0 * 528 + (r0 + r) * 33 + lane]);
                __stcg(&dst[(size_t)(b0 + r0 + r) * Hsz + h0c + lane], v);
            }
        }
        if (m == 1 && kh == 0 && i >= 1) {             // h1_{i-1}
            float* dst = g_h1[(i - 1) & 1];
#pragma unroll
            for (int r = 0; r < 4; ++r) {
                float v = tanh_fast(bias1 + acc[r]
                                    + sRed[1 * 528 + (r0 + r) * 33 + lane]
                                    + sRed[2 * 528 + (r0 + r) * 33 + lane]
                                    + sRed[3 * 528 + (r0 + r) * 33 + lane]);
                __stcg(&dst[(size_t)(b0 + r0 + r) * Hsz + h0c + lane], v);
            }
        }

        GRID_BARRIER((unsigned int)(i + 2));
    }

    // ================= phase 3: head (16 CTAs, one per batch group) =================
    if ((cta & 7) == 0 && warp < 8) {
        const float bo = bout[0];
#pragma unroll
        for (int rr = 0; rr < 2; ++rr) {
            const int b = b0 + warp * 2 + rr;
            const float* h = g_h1[(Ssz - 1) & 1] + (size_t)b * Hsz;
            float s = 0.0f;
#pragma unroll
            for (int j = 0; j < 8; ++j)
                s += __ldcg(&h[lane + 32 * j]) * Wout[lane + 32 * j];
#pragma unroll
            for (int o = 16; o > 0; o >>= 1) s += __shfl_down_sync(0xFFFFFFFFu, s, o);
            if (lane == 0) out[b] = 1.0f / (1.0f + expf(-(s + bo)));
        }
    }
#undef GRID_BARRIER
}

// ---------------- launch ----------------
extern "C" void kernel_launch(void* const* d_in, const int* in_sizes, int n_in,
                              void* d_out, int out_size) {
    const float* x    = (const float*)d_in[0];
    const float* Wih0 = (const float*)d_in[1];
    const float* Whh0 = (const float*)d_in[2];
    const float* bih0 = (const float*)d_in[3];
    const float* bhh0 = (const float*)d_in[4];
    const float* Wih1 = (const float*)d_in[5];
    const float* Whh1 = (const float*)d_in[6];
    const float* bih1 = (const float*)d_in[7];
    const float* bhh1 = (const float*)d_in[8];
    const float* Wout = (const float*)d_in[9];
    const float* bout = (const float*)d_in[10];
    float* out = (float*)d_out;

    const int smem_bytes = (3 * 8192 + 2 * 16 * WPAD + 4 * 16 * 33) * (int)sizeof(float); // 140,032 B
    static int configured = 0;
    if (!configured) {
        cudaFuncSetAttribute(fused_kernel, cudaFuncAttributeMaxDynamicSharedMemorySize, smem_bytes);
        configured = 1;
    }

    fused_kernel<<<NCTA, NTHR, smem_bytes>>>(x, Wih0, Whh0, bih0, bhh0,
                                             Wih1, Whh1, bih1, bhh1,
                                             Wout, bout, out);
}

// round 7
// speedup vs baseline: 2.2093x; 1.4280x over previous
#include <cuda_runtime.h>
#include <math.h>
#include <stdint.h>

#define Bsz 256
#define Ssz 2048
#define Dsz 64
#define Hsz 256
#define NCTA 128          // persistent CTAs, 1/SM, all co-resident
#define NTHR 512          // 16 warps: rq=warp&3, mm=(warp>>2)&1, kh=warp>>3
#define WPAD 260          // state row stride (floats)

// ---------------- device scratch ----------------
__device__ float g_pre0p[(size_t)NCTA * Ssz * 512];  // private pre0 [cta][s][row16][lane32]
__device__ float g_h0[2][Bsz * Hsz];                 // layer-0 state, double buffered
__device__ float g_h1[2][Bsz * Hsz];                 // layer-1 state, double buffered
__device__ unsigned int g_flags[NCTA];               // barrier flags (zeroed by init each launch)

__device__ __forceinline__ float tanh_fast(float x) {
    float y; asm("tanh.approx.f32 %0, %1;" : "=f"(y) : "f"(x)); return y;
}

// ---------------- init: zero flags + seed states (graph-ordered before fused) ----------------
__global__ void init_kernel() {
    const int idx = blockIdx.x * blockDim.x + threadIdx.x;
    if (idx < NCTA) g_flags[idx] = 0u;
    if (idx < Bsz * Hsz) {
        g_h0[1][idx] = 0.0f;
        g_h1[1][idx] = 0.0f;
    }
}

__global__ void __launch_bounds__(NTHR, 1)
fused_kernel(const float* __restrict__ x,
             const float* __restrict__ Wih0,
             const float* __restrict__ Whh0,
             const float* __restrict__ bih0,
             const float* __restrict__ bhh0,
             const float* __restrict__ Wih1,
             const float* __restrict__ Whh1,
             const float* __restrict__ bih1,
             const float* __restrict__ bhh1,
             const float* __restrict__ Wout,
             const float* __restrict__ bout,
             float* __restrict__ out) {
    extern __shared__ float smem[];
    float* sW   = smem;                      // 3*8192 f : weights [m][kq][col][4]
    float* sH0  = sW  + 3 * 8192;            // [16][WPAD]  h0_{i-1}
    float* sH1  = sH0 + 16 * WPAD;           // [16][WPAD]  h1_{i-2}
    float* sRed = sH1 + 16 * WPAD;           // 2 tiles of [16][33] partials

    const int tid  = threadIdx.x;
    const int cta  = blockIdx.x;
    const int grp8 = (cta >> 3) * 8;          // first CTA of this batch group
    const int b0   = (cta >> 3) * 16;         // 16 batch rows
    const int h0c  = (cta & 7) * 32;          // 32 h columns
    const int lane = tid & 31;
    const int warp = tid >> 5;                // 0..15
    const int rq   = warp & 3;                // row quad (== SMSP id: balanced)
    const int mm   = (warp >> 2) & 1;         // 0: Whh0 | 1: Wih1+Whh1
    const int kh   = warp >> 3;               // k half
    const int r0   = rq * 4;

    // ================= phase 1: pre0_priv = x @ Wih0^T + (b_ih0+b_hh0) =================
    {
        for (int it = tid; it < 32 * 16; it += NTHR) {
            const int col = it >> 4, kq = it & 15;
            *(float4*)(sW + (kq * 32 + col) * 4) =
                *(const float4*)(Wih0 + (size_t)(h0c + col) * Dsz + kq * 4);
        }
        __syncthreads();
        const float bsum = bih0[h0c + lane] + bhh0[h0c + lane];

        for (int s = warp; s < Ssz; s += 16) {
            float* dst = g_pre0p + ((size_t)cta * Ssz + s) * 512;
#pragma unroll 2
            for (int r = 0; r < 16; ++r) {
                const float4* xr = (const float4*)(x + ((size_t)(b0 + r) * Ssz + s) * Dsz);
                float a = 0.0f;
#pragma unroll
                for (int c2 = 0; c2 < 2; ++c2) {
                    float4 xv[8];
#pragma unroll
                    for (int q = 0; q < 8; ++q) xv[q] = __ldg(xr + c2 * 8 + q);
#pragma unroll
                    for (int q = 0; q < 8; ++q) {
                        float4 w = *(const float4*)(sW + ((c2 * 8 + q) * 32 + lane) * 4);
                        a += w.x * xv[q].x + w.y * xv[q].y + w.z * xv[q].z + w.w * xv[q].w;
                    }
                }
                dst[r * 32 + lane] = a + bsum;
            }
        }
        __syncthreads();   // sW about to be overwritten
    }

    // ---- one-time recurrence weight load: [col][k] -> smem [m][kq][col][4] ----
    for (int it = tid; it < 32 * 64; it += NTHR) {
        const int col = it >> 6, kq = it & 63;
        const size_t gi = (size_t)(h0c + col) * Hsz + kq * 4;
        const int    si = (kq * 32 + col) * 4;
        *(float4*)(sW + 0 * 8192 + si) = *(const float4*)(Whh0 + gi);
        *(float4*)(sW + 1 * 8192 + si) = *(const float4*)(Wih1 + gi);
        *(float4*)(sW + 2 * 8192 + si) = *(const float4*)(Whh1 + gi);
    }
    const float bias1 = bih1[h0c + lane] + bhh1[h0c + lane];

    // ---- group-local barrier: sync only the 8 CTAs of this batch group ----
    // FENCED: whether this thread must fence (it stored state this step).
#define GROUP_BARRIER(VAL, FENCED) do {                                    \
        if (FENCED) __threadfence();                                       \
        __syncthreads();                                                   \
        if (tid == 0) g_flags[cta] = (VAL);                                \
        if (tid < 8) {                                                     \
            volatile unsigned int* pf = &g_flags[grp8 + tid];              \
            const unsigned int tgt = (VAL);                                \
            while ((int)(*pf - tgt) < 0) { }                               \
        }                                                                  \
        __syncthreads();                                                   \
    } while (0)

    GROUP_BARRIER(1u, true);   // pre0 + (init kernel's seeds) visible

    // ---- per-warp constant pointers for the recurrence ----
    const float* WpA = sW + (mm == 0 ? 0 : 8192)  + kh * 4096;  // Whh0 or Wih1
    const float* WpB = sW + 16384 + kh * 4096;                  // Whh1 (mm1 only)
    const float* S0p = sH0 + r0 * WPAD + kh * 128;
    const float* S1p = sH1 + r0 * WPAD + kh * 128;
    float* redTile = sRed + mm * 528;                            // kh1 warps write

    // ================= phase 2: fused two-layer recurrence =================
    for (int i = 0; i <= Ssz; ++i) {
        // ---- stage previous states into SMEM (L2-coherent) ----
        if (tid < 256) {
            const int row = tid >> 4, c16 = tid & 15;
            const float* src = g_h0[(i + 1) & 1] + (size_t)(b0 + row) * Hsz;
            float* dst = sH0 + row * WPAD;
#pragma unroll
            for (int q = 0; q < 4; ++q)
                *(float4*)(dst + (c16 + q * 16) * 4) =
                    __ldcg((const float4*)(src + (c16 + q * 16) * 4));
        } else if (i >= 1) {
            const int t = tid - 256, row = t >> 4, c16 = t & 15;
            const float* src = g_h1[i & 1] + (size_t)(b0 + row) * Hsz;
            float* dst = sH1 + row * WPAD;
#pragma unroll
            for (int q = 0; q < 4; ++q)
                *(float4*)(dst + (c16 + q * 16) * 4) =
                    __ldcg((const float4*)(src + (c16 + q * 16) * 4));
        }
        // pre0 prefetch for h0 finalizers (mm0, kh0)
        float p[4];
        if (mm == 0 && kh == 0 && i < Ssz) {
            const float* pp = g_pre0p + ((size_t)cta * Ssz + i) * 512;
#pragma unroll
            for (int r = 0; r < 4; ++r) p[r] = pp[(r0 + r) * 32 + lane];
        }
        __syncthreads();

        // ---- compute: mm0 = Whh0; mm1 = Wih1 + Whh1 fused ----
        float acc[4] = {0.f, 0.f, 0.f, 0.f};
        const bool active = (mm == 0) ? (i < Ssz) : (i >= 1);
        if (active) {
            if (mm == 0) {
#pragma unroll 8
                for (int kq = 0; kq < 32; ++kq) {
                    float4 w = *(const float4*)(WpA + (kq * 32 + lane) * 4);
#pragma unroll
                    for (int r = 0; r < 4; ++r) {
                        float4 v = *(const float4*)(S0p + r * WPAD + kq * 4);
                        acc[r] += w.x * v.x + w.y * v.y + w.z * v.z + w.w * v.w;
                    }
                }
            } else {
#pragma unroll 4
                for (int kq = 0; kq < 32; ++kq) {
                    float4 wa = *(const float4*)(WpA + (kq * 32 + lane) * 4);
                    float4 wb = *(const float4*)(WpB + (kq * 32 + lane) * 4);
#pragma unroll
                    for (int r = 0; r < 4; ++r) {
                        float4 v0 = *(const float4*)(S0p + r * WPAD + kq * 4);
                        float4 v1 = *(const float4*)(S1p + r * WPAD + kq * 4);
                        acc[r] += wa.x * v0.x + wa.y * v0.y + wa.z * v0.z + wa.w * v0.w;
                        acc[r] += wb.x * v1.x + wb.y * v1.y + wb.z * v1.z + wb.w * v1.w;
                    }
                }
            }
            if (kh == 1) {
#pragma unroll
                for (int r = 0; r < 4; ++r) redTile[(r0 + r) * 33 + lane] = acc[r];
            }
        }
        __syncthreads();

        // ---- finalize (kh0 warps) ----
        bool stored = false;
        if (kh == 0) {
            if (mm == 0 && i < Ssz) {            // h0_i
                float* dst = g_h0[i & 1];
#pragma unroll
                for (int r = 0; r < 4; ++r) {
                    float v = tanh_fast(p[r] + acc[r] + sRed[0 * 528 + (r0 + r) * 33 + lane]);
                    __stcg(&dst[(size_t)(b0 + r0 + r) * Hsz + h0c + lane], v);
                }
                stored = true;
            }
            if (mm == 1 && i >= 1) {             // h1_{i-1}
                float* dst = g_h1[(i - 1) & 1];
#pragma unroll
                for (int r = 0; r < 4; ++r) {
                    float v = tanh_fast(bias1 + acc[r] + sRed[1 * 528 + (r0 + r) * 33 + lane]);
                    __stcg(&dst[(size_t)(b0 + r0 + r) * Hsz + h0c + lane], v);
                }
                stored = true;
            }
        }

        GROUP_BARRIER((unsigned int)(i + 2), stored);
    }

    // ================= phase 3: head (16 CTAs, one per batch group) =================
    if ((cta & 7) == 0 && warp < 8) {
        const float bo = bout[0];
#pragma unroll
        for (int rr = 0; rr < 2; ++rr) {
            const int b = b0 + warp * 2 + rr;
            const float* h = g_h1[(Ssz - 1) & 1] + (size_t)b * Hsz;
            float s = 0.0f;
#pragma unroll
            for (int j = 0; j < 8; ++j)
                s += __ldcg(&h[lane + 32 * j]) * Wout[lane + 32 * j];
#pragma unroll
            for (int o = 16; o > 0; o >>= 1) s += __shfl_down_sync(0xFFFFFFFFu, s, o);
            if (lane == 0) out[b] = 1.0f / (1.0f + expf(-(s + bo)));
        }
    }
#undef GROUP_BARRIER
}

// ---------------- launch ----------------
extern "C" void kernel_launch(void* const* d_in, const int* in_sizes, int n_in,
                              void* d_out, int out_size) {
    const float* x    = (const float*)d_in[0];
    const float* Wih0 = (const float*)d_in[1];
    const float* Whh0 = (const float*)d_in[2];
    const float* bih0 = (const float*)d_in[3];
    const float* bhh0 = (const float*)d_in[4];
    const float* Wih1 = (const float*)d_in[5];
    const float* Whh1 = (const float*)d_in[6];
    const float* bih1 = (const float*)d_in[7];
    const float* bhh1 = (const float*)d_in[8];
    const float* Wout = (const float*)d_in[9];
    const float* bout = (const float*)d_in[10];
    float* out = (float*)d_out;

    const int smem_bytes = (3 * 8192 + 2 * 16 * WPAD + 2 * 16 * 33) * (int)sizeof(float); // 135,808 B
    static int configured = 0;
    if (!configured) {
        cudaFuncSetAttribute(fused_kernel, cudaFuncAttributeMaxDynamicSharedMemorySize, smem_bytes);
        configured = 1;
    }

    init_kernel<<<(Bsz * Hsz + 511) / 512, 512>>>();
    fused_kernel<<<NCTA, NTHR, smem_bytes>>>(x, Wih0, Whh0, bih0, bhh0,
                                             Wih1, Whh1, bih1, bhh1,
                                             Wout, bout, out);
}

// round 9
// speedup vs baseline: 2.6351x; 1.1927x over previous
#include <cuda_runtime.h>
#include <math.h>
#include <stdint.h>

#define Bsz 256
#define Ssz 2048
#define Dsz 64
#define Hsz 256
#define NCTA 128          // persistent CTAs, 1/SM, all co-resident
#define NTHR 512          // 16 warps: 12 compute (m x kQ), 4 util
#define WPAD 260          // state row stride (floats); 1040B, 16B-aligned

// ---------------- device scratch ----------------
__device__ float g_pre0p[(size_t)NCTA * Ssz * 512];  // private pre0 [cta][s][row16][lane32]
__device__ float g_h0[2][Bsz * Hsz];                 // layer-0 state, double buffered
__device__ float g_h1[2][Bsz * Hsz];                 // layer-1 state, double buffered
__device__ unsigned int g_flags[NCTA];               // barrier flags (zeroed by init each launch)

__device__ __forceinline__ float tanh_fast(float x) {
    float y; asm("tanh.approx.f32 %0, %1;" : "=f"(y) : "f"(x)); return y;
}
// packed fp32x2 FMA (Blackwell): d = a*b + c elementwise on 2 packed floats
__device__ __forceinline__ unsigned long long fma2(unsigned long long a,
                                                   unsigned long long b,
                                                   unsigned long long c) {
    unsigned long long d;
    asm("fma.rn.f32x2 %0, %1, %2, %3;" : "=l"(d) : "l"(a), "l"(b), "l"(c));
    return d;
}
__device__ __forceinline__ float hsum2(unsigned long long a) {
    float2 f = *reinterpret_cast<float2*>(&a);
    return f.x + f.y;
}

// ---------------- init: zero flags + seed states ----------------
__global__ void init_kernel() {
    const int idx = blockIdx.x * blockDim.x + threadIdx.x;
    if (idx < NCTA) g_flags[idx] = 0u;
    if (idx < Bsz * Hsz) {
        g_h0[1][idx] = 0.0f;
        g_h1[1][idx] = 0.0f;
    }
}

__global__ void __launch_bounds__(NTHR, 1)
fused_kernel(const float* __restrict__ x,
             const float* __restrict__ Wih0,
             const float* __restrict__ Whh0,
             const float* __restrict__ bih0,
             const float* __restrict__ bhh0,
             const float* __restrict__ Wih1,
             const float* __restrict__ Whh1,
             const float* __restrict__ bih1,
             const float* __restrict__ bhh1,
             const float* __restrict__ Wout,
             const float* __restrict__ bout,
             float* __restrict__ out) {
    extern __shared__ float smem[];
    float* sH0  = smem;                      // [16][WPAD]  h0_{i-1}   (pre0 reuses as sW)
    float* sH1  = sH0 + 16 * WPAD;           // [16][WPAD]  h1_{i-2}
    float* sRed = sH1 + 16 * WPAD;           // 12 tiles of [16][33] partials

    const int tid  = threadIdx.x;
    const int cta  = blockIdx.x;
    const int grp8 = (cta >> 3) * 8;
    const int b0   = (cta >> 3) * 16;         // 16 batch rows
    const int h0c  = (cta & 7) * 32;          // 32 h columns
    const int lane = tid & 31;
    const int warp = tid >> 5;                // 0..15
    // compute warps 0..11: m = warp>>2 (0=Whh0,1=Wih1,2=Whh1), kQ = warp&3 (=SMSP)
    const int m  = warp >> 2;
    const int kQ = warp & 3;
    // util warps 12..15
    const int uw = warp - 12;

    // ================= phase 1: pre0_priv = x @ Wih0^T + (b_ih0+b_hh0) =================
    {
        float* sW = sH0;   // 2048 floats, overwritten later by state staging
        for (int it = tid; it < 32 * 16; it += NTHR) {
            const int col = it >> 4, kq = it & 15;
            *(float4*)(sW + (kq * 32 + col) * 4) =
                *(const float4*)(Wih0 + (size_t)(h0c + col) * Dsz + kq * 4);
        }
        __syncthreads();
        const float bsum = bih0[h0c + lane] + bhh0[h0c + lane];

        for (int s = warp; s < Ssz; s += 16) {
            float* dst = g_pre0p + ((size_t)cta * Ssz + s) * 512;
#pragma unroll 2
            for (int r = 0; r < 16; ++r) {
                const float4* xr = (const float4*)(x + ((size_t)(b0 + r) * Ssz + s) * Dsz);
                float a = 0.0f;
#pragma unroll
                for (int c2 = 0; c2 < 2; ++c2) {
                    float4 xv[8];
#pragma unroll
                    for (int q = 0; q < 8; ++q) xv[q] = __ldg(xr + c2 * 8 + q);
#pragma unroll
                    for (int q = 0; q < 8; ++q) {
                        float4 w = *(const float4*)(sW + ((c2 * 8 + q) * 32 + lane) * 4);
                        a += w.x * xv[q].x + w.y * xv[q].y + w.z * xv[q].z + w.w * xv[q].w;
                    }
                }
                dst[r * 32 + lane] = a + bsum;
            }
        }
        __syncthreads();   // sW region about to be reused
    }

    // ---- compute warps: load own 64 weights into registers (persist all steps) ----
    unsigned long long w0[16], w1[16];
    if (warp < 12) {
        const float* Wsrc = (m == 0) ? Whh0 : (m == 1) ? Wih1 : Whh1;
        const float* base = Wsrc + (size_t)(h0c + lane) * Hsz + kQ * 64;
#pragma unroll
        for (int j = 0; j < 16; ++j) {
            ulonglong2 t = *(const ulonglong2*)(base + j * 4);
            w0[j] = t.x; w1[j] = t.y;
        }
    }
    const float bias1 = bih1[h0c + lane] + bhh1[h0c + lane];

    // ---- group-local barrier (sync the 8 CTAs of this batch group) ----
#define GROUP_BARRIER(VAL, FENCED) do {                                    \
        if (FENCED) __threadfence();                                       \
        __syncthreads();                                                   \
        if (tid == 0) g_flags[cta] = (VAL);                                \
        if (tid < 8) {                                                     \
            volatile unsigned int* pf = &g_flags[grp8 + tid];              \
            const unsigned int tgt = (VAL);                                \
            while ((int)(*pf - tgt) < 0) { }                               \
        }                                                                  \
        __syncthreads();                                                   \
    } while (0)

    GROUP_BARRIER(1u, true);   // pre0 + init seeds visible

    // ================= phase 2: fused two-layer recurrence =================
    for (int i = 0; i <= Ssz; ++i) {
        // ---- stage previous states: 256 threads per half, FULL 256-float rows ----
        {
            const int half = tid >> 8;            // 0: h0, 1: h1
            const int t    = tid & 255;
            const int row  = t >> 4, c16 = t & 15;
            const float* src = half ? (g_h1[i & 1]       + (size_t)(b0 + row) * Hsz)
                                    : (g_h0[(i + 1) & 1] + (size_t)(b0 + row) * Hsz);
            float* dst = (half ? sH1 : sH0) + row * WPAD;
#pragma unroll
            for (int q = 0; q < 4; ++q)
                *(float4*)(dst + (c16 + q * 16) * 4) =
                    __ldcg((const float4*)(src + (c16 + q * 16) * 4));
        }
        __syncthreads();

        float p[4];
        if (warp < 12) {
            // ---- compute partials: 16 rows x (lane col) over own 64-k quarter ----
            const bool active = (m == 0) ? (i < Ssz) : (i >= 1);
            if (active) {
                const float* Sp = ((m == 2) ? sH1 : sH0) + kQ * 64;
                float* red = sRed + (m * 4 + kQ) * 528;
#pragma unroll 2
                for (int r = 0; r < 16; ++r) {
                    unsigned long long a0 = 0ull, a1 = 0ull;
                    const ulonglong2* vp = (const ulonglong2*)(Sp + r * WPAD);
#pragma unroll
                    for (int j = 0; j < 16; ++j) {
                        ulonglong2 v = vp[j];
                        a0 = fma2(w0[j], v.x, a0);
                        a1 = fma2(w1[j], v.y, a1);
                    }
                    red[r * 33 + lane] = hsum2(a0) + hsum2(a1);
                }
            }
        } else {
            // ---- util: prefetch pre0 for this step's h0 finalize ----
            if (i < Ssz) {
                const float* pp = g_pre0p + ((size_t)cta * Ssz + i) * 512;
#pragma unroll
                for (int rr = 0; rr < 4; ++rr)
                    p[rr] = pp[(uw * 4 + rr) * 32 + lane];
            }
        }
        __syncthreads();

        // ---- finalize (util warps): reduce partials, tanh, store state ----
        bool stored = false;
        if (warp >= 12) {
            if (i < Ssz) {            // h0_i
                float* dst = g_h0[i & 1];
#pragma unroll
                for (int rr = 0; rr < 4; ++rr) {
                    const int r = uw * 4 + rr;
                    float s = p[rr];
#pragma unroll
                    for (int q = 0; q < 4; ++q) s += sRed[q * 528 + r * 33 + lane];
                    __stcg(&dst[(size_t)(b0 + r) * Hsz + h0c + lane], tanh_fast(s));
                }
                stored = true;
            }
            if (i >= 1) {             // h1_{i-1}
                float* dst = g_h1[(i - 1) & 1];
#pragma unroll
                for (int rr = 0; rr < 4; ++rr) {
                    const int r = uw * 4 + rr;
                    float s = bias1;
#pragma unroll
                    for (int q = 4; q < 12; ++q) s += sRed[q * 528 + r * 33 + lane];
                    __stcg(&dst[(size_t)(b0 + r) * Hsz + h0c + lane], tanh_fast(s));
                }
                stored = true;
            }
        }

        GROUP_BARRIER((unsigned int)(i + 2), stored);
    }

    // ================= phase 3: head (16 CTAs, one per batch group) =================
    if ((cta & 7) == 0 && warp < 8) {
        const float bo = bout[0];
#pragma unroll
        for (int rr = 0; rr < 2; ++rr) {
            const int b = b0 + warp * 2 + rr;
            const float* h = g_h1[(Ssz - 1) & 1] + (size_t)b * Hsz;
            float s = 0.0f;
#pragma unroll
            for (int j = 0; j < 8; ++j)
                s += __ldcg(&h[lane + 32 * j]) * Wout[lane + 32 * j];
#pragma unroll
            for (int o = 16; o > 0; o >>= 1) s += __shfl_down_sync(0xFFFFFFFFu, s, o);
            if (lane == 0) out[b] = 1.0f / (1.0f + expf(-(s + bo)));
        }
    }
#undef GROUP_BARRIER
}

// ---------------- launch ----------------
extern "C" void kernel_launch(void* const* d_in, const int* in_sizes, int n_in,
                              void* d_out, int out_size) {
    const float* x    = (const float*)d_in[0];
    const float* Wih0 = (const float*)d_in[1];
    const float* Whh0 = (const float*)d_in[2];
    const float* bih0 = (const float*)d_in[3];
    const float* bhh0 = (const float*)d_in[4];
    const float* Wih1 = (const float*)d_in[5];
    const float* Whh1 = (const float*)d_in[6];
    const float* bih1 = (const float*)d_in[7];
    const float* bhh1 = (const float*)d_in[8];
    const float* Wout = (const float*)d_in[9];
    const float* bout = (const float*)d_in[10];
    float* out = (float*)d_out;

    // smem: 2*16*WPAD + 12*16*33 floats = 8320 + 6336 = 14656 floats = 58,624 B
    const int smem_bytes = (2 * 16 * WPAD + 12 * 16 * 33) * (int)sizeof(float);
    static int configured = 0;
    if (!configured) {
        cudaFuncSetAttribute(fused_kernel, cudaFuncAttributeMaxDynamicSharedMemorySize, smem_bytes);
        configured = 1;
    }

    init_kernel<<<(Bsz * Hsz + 511) / 512, 512>>>();
    fused_kernel<<<NCTA, NTHR, smem_bytes>>>(x, Wih0, Whh0, bih0, bhh0,
                                             Wih1, Whh1, bih1, bhh1,
                                             Wout, bout, out);
}